// round 1
// baseline (speedup 1.0000x reference)
#include <cuda_runtime.h>

typedef unsigned long long ull;
typedef unsigned int u32;

#define NPOS   21824
#define BATCH  8
#define KTOP   1000
#define NCLS   80

// Scratch (no allocation allowed -> __device__ globals)
__device__ ull    g_keys[BATCH * NPOS];
__device__ float4 g_boxes[BATCH * NPOS];
__device__ float  g_kind[BATCH * NPOS];

__constant__ int   c_off[5]    = {0, 16384, 20480, 21504, 21760};
__constant__ int   c_logw[5]   = {7, 6, 5, 4, 3};
__constant__ float c_stride[5] = {8.f, 16.f, 32.f, 64.f, 128.f};

struct Ptrs { const float* cls[5]; const float* reg[5]; };

// ---------------------------------------------------------------------------
// Kernel 1: decode all levels -> per-position (key, box, kind)
// key = (float_bits(score) << 32) | (0xFFFFFFFF - pos)
//   - monotone in (score desc, index asc) => reproduces jax top_k tie-break
// ---------------------------------------------------------------------------
__global__ void decode_kernel(Ptrs p) {
    int gid = blockIdx.x * blockDim.x + threadIdx.x;
    if (gid >= BATCH * NPOS) return;
    int b   = gid / NPOS;
    int pos = gid - b * NPOS;

    int lev = 0;
    if      (pos >= c_off[4]) lev = 4;
    else if (pos >= c_off[3]) lev = 3;
    else if (pos >= c_off[2]) lev = 2;
    else if (pos >= c_off[1]) lev = 1;

    int local = pos - c_off[lev];
    int lw = c_logw[lev];
    int w  = 1 << lw;
    int hw = w * w;
    int y  = local >> lw;
    int x  = local & (w - 1);

    // class max / argmax (first-index tie-break = jnp.argmax)
    const float* __restrict__ cbase = p.cls[lev] + (size_t)b * NCLS * hw + local;
    float best = cbase[0];
    int   bi   = 0;
    #pragma unroll 8
    for (int c = 1; c < NCLS; c++) {
        float v = cbase[(size_t)c * hw];
        if (v > best) { best = v; bi = c; }
    }
    float score = (best > 0.05f) ? best : 0.0f;

    const float* __restrict__ rbase = p.reg[lev] + (size_t)b * 4 * hw + local;
    float s  = c_stride[lev];
    float r0 = rbase[0]      * s;
    float r1 = rbase[hw]     * s;
    float r2 = rbase[2 * hw] * s;
    float r3 = rbase[3 * hw] * s;
    float cx = ((float)x + 0.5f) * s;
    float cy = ((float)y + 0.5f) * s;

    g_boxes[gid] = make_float4(cx - r0, cy - r1, cx + r2, cy + r3);
    g_kind[gid]  = (float)bi;
    g_keys[gid]  = (((ull)__float_as_uint(score)) << 32) |
                   (ull)(0xFFFFFFFFu - (u32)pos);
}

// ---------------------------------------------------------------------------
// Kernel 2: per-image (one block each):
//   radix-select 1000th key -> compact -> bitonic sort 1024 ->
//   build 1000x1000 suppression bit-matrix in shared -> 1-warp serial sweep ->
//   write output rows [x1,y1,x2,y2,kind,score]
// ---------------------------------------------------------------------------
#define SM_TOP   0
#define SM_BOX   (8192)
#define SM_KIND  (8192 + 16384)
#define SM_SCORE (8192 + 16384 + 4096)
#define SM_AREA  (8192 + 16384 + 8192)
#define SM_MASK  (8192 + 16384 + 12288)
#define SM_TOTAL (SM_MASK + 1024 * 32 * 4)   // 167936 bytes

__global__ void __launch_bounds__(1024, 1) topk_nms_kernel(float* __restrict__ out) {
    extern __shared__ unsigned char smraw[];
    ull*    s_top   = (ull*)   (smraw + SM_TOP);
    float4* s_box   = (float4*)(smraw + SM_BOX);
    float*  s_kind  = (float*) (smraw + SM_KIND);
    float*  s_score = (float*) (smraw + SM_SCORE);
    float*  s_area  = (float*) (smraw + SM_AREA);
    u32*    s_mask  = (u32*)   (smraw + SM_MASK);

    __shared__ u32 s_hist[256];
    __shared__ int s_cnt, s_digit, s_rem;
    __shared__ u32 s_remw[32];

    int tid  = threadIdx.x;
    int lane = tid & 31;
    int b    = blockIdx.x;
    const ull* __restrict__ keys = g_keys + (size_t)b * NPOS;

    // ---- exact radix select of the KTOP-th largest key (keys are unique) ----
    ull prefix    = 0;
    int remaining = KTOP;
    for (int shift = 56; shift >= 0; shift -= 8) {
        if (tid < 256) s_hist[tid] = 0;
        __syncthreads();
        ull himask = (shift == 56) ? 0ull : (~0ull << (shift + 8));
        for (int i = tid; i < NPOS; i += 1024) {
            ull k = keys[i];
            if ((k & himask) == prefix) {
                u32 d     = (u32)(k >> shift) & 255u;
                u32 act   = __activemask();
                u32 peers = __match_any_sync(act, d);
                int leader = __ffs(peers) - 1;
                if (lane == leader) atomicAdd(&s_hist[d], (u32)__popc(peers));
            }
        }
        __syncthreads();
        if (tid == 0) {
            int acc = 0, d = 255;
            for (; d >= 0; d--) {
                int c = (int)s_hist[d];
                if (acc + c >= remaining) break;
                acc += c;
            }
            s_digit = d;
            s_rem   = remaining - acc;
        }
        __syncthreads();
        prefix |= ((ull)(u32)s_digit) << shift;
        remaining = s_rem;
    }
    // prefix == exact KTOP-th largest key

    // ---- compact: all keys >= prefix (exactly KTOP of them) ----
    if (tid == 0) s_cnt = 0;
    s_top[tid] = 0;     // padding sorts to the end
    __syncthreads();
    for (int i = tid; i < NPOS; i += 1024) {
        ull k = keys[i];
        if (k >= prefix) {
            u32 act = __activemask();
            u32 lt  = act & ((1u << lane) - 1u);
            int rank   = __popc(lt);
            int leader = __ffs(act) - 1;
            int base = 0;
            if (lane == leader) base = atomicAdd(&s_cnt, __popc(act));
            base = __shfl_sync(act, base, leader);
            s_top[base + rank] = k;
        }
    }

    // ---- bitonic sort 1024 keys, descending ----
    for (int k2 = 2; k2 <= 1024; k2 <<= 1) {
        for (int j = k2 >> 1; j > 0; j >>= 1) {
            __syncthreads();
            int ixj = tid ^ j;
            if (ixj > tid) {
                ull a = s_top[tid], c = s_top[ixj];
                bool desc = ((tid & k2) == 0);
                if (desc ? (a < c) : (a > c)) { s_top[tid] = c; s_top[ixj] = a; }
            }
        }
    }
    __syncthreads();

    // ---- gather selected boxes/kind/score into shared ----
    {
        ull k    = s_top[tid];
        float sc = __uint_as_float((u32)(k >> 32));
        u32 idx  = 0xFFFFFFFFu - (u32)(k & 0xFFFFFFFFull);
        float4 bx = make_float4(0.f, 0.f, 0.f, 0.f);
        float  kd = 0.f;
        if (tid < KTOP) {
            bx = g_boxes[(size_t)b * NPOS + idx];
            kd = g_kind[(size_t)b * NPOS + idx];
        }
        s_box[tid]   = bx;
        s_kind[tid]  = kd;
        s_score[tid] = sc;
        s_area[tid]  = fmaxf(bx.z - bx.x, 0.f) * fmaxf(bx.w - bx.y, 0.f);
    }
    __syncthreads();

    // ---- suppression bit-matrix: bit j of word (i,w) => i suppresses j ----
    for (int t = tid; t < 1024 * 32; t += 1024) {
        int i = t >> 5;
        int w = t & 31;
        u32 m = 0;
        int j0 = w * 32;
        if (i < KTOP && (j0 + 31) > i) {
            float4 bi = s_box[i];
            float  ai = s_area[i];
            float  ki = s_kind[i];
            #pragma unroll 8
            for (int bit = 0; bit < 32; bit++) {
                int j = j0 + bit;
                if (j > i && j < KTOP) {
                    float4 bj = s_box[j];
                    if (s_kind[j] == ki) {
                        float xx1 = fmaxf(bi.x, bj.x);
                        float yy1 = fmaxf(bi.y, bj.y);
                        float xx2 = fminf(bi.z, bj.z);
                        float yy2 = fminf(bi.w, bj.w);
                        float inter = fmaxf(xx2 - xx1, 0.f) * fmaxf(yy2 - yy1, 0.f);
                        float iou   = inter / (ai + s_area[j] - inter + 1e-9f);
                        if (iou > 0.5f) m |= (1u << bit);
                    }
                }
            }
        }
        s_mask[t] = m;
    }
    __syncthreads();

    // ---- serial greedy sweep on warp 0; removed bitset lives in registers ----
    if (tid < 32) {
        u32 rem = 0;
        for (int i = 0; i < KTOP; i++) {
            u32 wv = __shfl_sync(0xffffffffu, rem, i >> 5);
            if (!((wv >> (i & 31)) & 1u)) {
                rem |= s_mask[i * 32 + tid];
            }
        }
        s_remw[tid] = rem;
    }
    __syncthreads();

    // ---- output: boxes/kind always, score zeroed unless kept & positive ----
    if (tid < KTOP) {
        bool removed = (s_remw[tid >> 5] >> (tid & 31)) & 1u;
        float sc = s_score[tid];
        float out_sc = (!removed && sc > 0.0f) ? sc : 0.0f;
        float4 bx = s_box[tid];
        float* o = out + ((size_t)b * KTOP + tid) * 6;
        o[0] = bx.x; o[1] = bx.y; o[2] = bx.z; o[3] = bx.w;
        o[4] = s_kind[tid];
        o[5] = out_sc;
    }
}

// ---------------------------------------------------------------------------
extern "C" void kernel_launch(void* const* d_in, const int* in_sizes, int n_in,
                              void* d_out, int out_size) {
    // Resolve input ordering at runtime:
    //  (a) signature order: cls0..4, cnt0..4, reg0..4  -> in_sizes[1] == 2621440 (cls1)
    //  (b) dict order:      cls0,cnt0,reg0, cls1,...   -> in_sizes[1] == 131072  (cnt0)
    bool dict_order = (in_sizes[1] != 2621440);
    Ptrs p;
    for (int i = 0; i < 5; i++) {
        if (dict_order) {
            p.cls[i] = (const float*)d_in[3 * i];
            p.reg[i] = (const float*)d_in[3 * i + 2];
        } else {
            p.cls[i] = (const float*)d_in[i];
            p.reg[i] = (const float*)d_in[10 + i];
        }
    }

    int total = BATCH * NPOS;
    decode_kernel<<<(total + 255) / 256, 256>>>(p);

    cudaFuncSetAttribute(topk_nms_kernel,
                         cudaFuncAttributeMaxDynamicSharedMemorySize, SM_TOTAL);
    topk_nms_kernel<<<BATCH, 1024, SM_TOTAL>>>((float*)d_out);
}

// round 4
// speedup vs baseline: 3.2258x; 3.2258x over previous
#include <cuda_runtime.h>

typedef unsigned long long ull;
typedef unsigned int u32;

#define NPOS   21824
#define BATCH  8
#define KTOP   1000
#define NCLS   80

// Scratch (no allocation allowed -> __device__ globals)
__device__ ull    g_keys[BATCH * NPOS];
__device__ float4 g_boxes[BATCH * NPOS];
__device__ float  g_kind[BATCH * NPOS];

// per-image selected top-1024 (SoA)
__device__ float4 g_top_box[BATCH * 1024];
__device__ float  g_top_kind[BATCH * 1024];
__device__ float  g_top_score[BATCH * 1024];
__device__ float  g_top_area[BATCH * 1024];
// suppression bit-matrix: [b][i][w], bit j-of-word => i suppresses j=w*32+bit
__device__ u32    g_mask[BATCH * 1024 * 32];

__constant__ int   c_off[5]    = {0, 16384, 20480, 21504, 21760};
__constant__ int   c_logw[5]   = {7, 6, 5, 4, 3};
__constant__ float c_stride[5] = {8.f, 16.f, 32.f, 64.f, 128.f};

struct Ptrs { const float* cls[5]; const float* reg[5]; };

// ---------------------------------------------------------------------------
// Kernel 1: decode all levels -> per-position (key, box, kind)
// key = (float_bits(score) << 32) | (0xFFFFFFFF - pos)
// ---------------------------------------------------------------------------
__global__ void decode_kernel(Ptrs p) {
    int gid = blockIdx.x * blockDim.x + threadIdx.x;
    if (gid >= BATCH * NPOS) return;
    int b   = gid / NPOS;
    int pos = gid - b * NPOS;

    int lev = 0;
    if      (pos >= c_off[4]) lev = 4;
    else if (pos >= c_off[3]) lev = 3;
    else if (pos >= c_off[2]) lev = 2;
    else if (pos >= c_off[1]) lev = 1;

    int local = pos - c_off[lev];
    int lw = c_logw[lev];
    int w  = 1 << lw;
    int hw = w * w;
    int y  = local >> lw;
    int x  = local & (w - 1);

    const float* __restrict__ cbase = p.cls[lev] + (size_t)b * NCLS * hw + local;
    float best = cbase[0];
    int   bi   = 0;
    #pragma unroll 8
    for (int c = 1; c < NCLS; c++) {
        float v = cbase[(size_t)c * hw];
        if (v > best) { best = v; bi = c; }
    }
    float score = (best > 0.05f) ? best : 0.0f;

    const float* __restrict__ rbase = p.reg[lev] + (size_t)b * 4 * hw + local;
    float s  = c_stride[lev];
    float r0 = rbase[0]      * s;
    float r1 = rbase[hw]     * s;
    float r2 = rbase[2 * hw] * s;
    float r3 = rbase[3 * hw] * s;
    float cx = ((float)x + 0.5f) * s;
    float cy = ((float)y + 0.5f) * s;

    g_boxes[gid] = make_float4(cx - r0, cy - r1, cx + r2, cy + r3);
    g_kind[gid]  = (float)bi;
    g_keys[gid]  = (((ull)__float_as_uint(score)) << 32) |
                   (ull)(0xFFFFFFFFu - (u32)pos);
}

// ---------------------------------------------------------------------------
// Kernel 2: per-image select top-1000 (exact radix select over shared copy),
//           bitonic sort 1024, gather into g_top_* SoA.
// ---------------------------------------------------------------------------
#define SEL_SMEM ((NPOS + 1024) * 8)   // keys + s_top = 182784 bytes

__global__ void __launch_bounds__(1024, 1) select_kernel() {
    extern __shared__ ull sm[];
    ull* s_keys = sm;            // NPOS
    ull* s_top  = sm + NPOS;     // 1024

    __shared__ u32 s_hist[256];
    __shared__ int s_cnt, s_digit, s_rem;

    int tid  = threadIdx.x;
    int lane = tid & 31;
    int b    = blockIdx.x;
    const ull* __restrict__ gk = g_keys + (size_t)b * NPOS;

    // stage all keys to shared once
    for (int i = tid; i < NPOS; i += 1024) s_keys[i] = gk[i];
    __syncthreads();

    // ---- exact radix select of KTOP-th largest key (keys are unique) ----
    ull prefix    = 0;
    int remaining = KTOP;
    for (int shift = 56; shift >= 0; shift -= 8) {
        if (tid < 256) s_hist[tid] = 0;
        __syncthreads();
        ull himask = (shift == 56) ? 0ull : (~0ull << (shift + 8));
        for (int i = tid; i < NPOS; i += 1024) {
            ull k = s_keys[i];
            if ((k & himask) == prefix) {
                u32 d     = (u32)(k >> shift) & 255u;
                u32 act   = __activemask();
                u32 peers = __match_any_sync(act, d);
                int leader = __ffs(peers) - 1;
                if (lane == leader) atomicAdd(&s_hist[d], (u32)__popc(peers));
            }
        }
        __syncthreads();
        if (tid == 0) {
            int acc = 0, d = 255;
            for (; d >= 0; d--) {
                int c = (int)s_hist[d];
                if (acc + c >= remaining) break;
                acc += c;
            }
            s_digit = d;
            s_rem   = remaining - acc;
        }
        __syncthreads();
        prefix |= ((ull)(u32)s_digit) << shift;
        remaining = s_rem;
    }

    // ---- compact: all keys >= prefix (exactly KTOP) ----
    if (tid == 0) s_cnt = 0;
    s_top[tid] = 0;
    __syncthreads();
    for (int i = tid; i < NPOS; i += 1024) {
        ull k = s_keys[i];
        if (k >= prefix) {
            u32 act = __activemask();
            u32 lt  = act & ((1u << lane) - 1u);
            int rank   = __popc(lt);
            int leader = __ffs(act) - 1;
            int base = 0;
            if (lane == leader) base = atomicAdd(&s_cnt, __popc(act));
            base = __shfl_sync(act, base, leader);
            s_top[base + rank] = k;
        }
    }

    // ---- bitonic sort 1024, descending ----
    for (int k2 = 2; k2 <= 1024; k2 <<= 1) {
        for (int j = k2 >> 1; j > 0; j >>= 1) {
            __syncthreads();
            int ixj = tid ^ j;
            if (ixj > tid) {
                ull a = s_top[tid], c = s_top[ixj];
                bool desc = ((tid & k2) == 0);
                if (desc ? (a < c) : (a > c)) { s_top[tid] = c; s_top[ixj] = a; }
            }
        }
    }
    __syncthreads();

    // ---- gather into global SoA ----
    {
        ull k    = s_top[tid];
        float sc = __uint_as_float((u32)(k >> 32));
        u32 idx  = 0xFFFFFFFFu - (u32)(k & 0xFFFFFFFFull);
        float4 bx = make_float4(0.f, 0.f, 0.f, 0.f);
        float  kd = 0.f;
        if (tid < KTOP) {
            bx = g_boxes[(size_t)b * NPOS + idx];
            kd = g_kind[(size_t)b * NPOS + idx];
        }
        int o = b * 1024 + tid;
        g_top_box[o]   = bx;
        g_top_kind[o]  = kd;
        g_top_score[o] = sc;
        g_top_area[o]  = fmaxf(bx.z - bx.x, 0.f) * fmaxf(bx.w - bx.y, 0.f);
    }
}

// ---------------------------------------------------------------------------
// Kernel 3: suppression bit-matrix, spread across chip.
// grid (16, BATCH), 256 threads. Block handles 64 i-rows of one image.
// Division-free IoU test: inter > 0.5*denom  <=>  iou > 0.5 (denom > 0).
// ---------------------------------------------------------------------------
__global__ void __launch_bounds__(256) mask_kernel() {
    __shared__ float s_x1[1024], s_y1[1024], s_x2[1024], s_y2[1024];
    __shared__ float s_area[1024], s_kind[1024];

    int tid = threadIdx.x;
    int b   = blockIdx.y;
    int r0  = blockIdx.x * 64;

    for (int t = tid; t < 1024; t += 256) {
        float4 bx = g_top_box[b * 1024 + t];
        s_x1[t] = bx.x; s_y1[t] = bx.y; s_x2[t] = bx.z; s_y2[t] = bx.w;
        s_area[t] = g_top_area[b * 1024 + t];
        s_kind[t] = g_top_kind[b * 1024 + t];
    }
    __syncthreads();

    int w  = tid & 31;          // word index (lane)
    int wi = tid >> 5;          // warp id 0..7
    int jbase = w * 32;

    for (int k = 0; k < 8; k++) {
        int i = r0 + wi * 8 + k;
        u32 m = 0;
        if (i < KTOP && (jbase + 31) > i) {
            float bx1 = s_x1[i], by1 = s_y1[i], bx2 = s_x2[i], by2 = s_y2[i];
            float ai = s_area[i], ki = s_kind[i];
            #pragma unroll
            for (int it = 0; it < 32; it++) {
                int jr = (it + w) & 31;       // rotate -> conflict-free banks
                int j  = jbase + jr;
                if (j > i && j < KTOP && s_kind[j] == ki) {
                    float xx1 = fmaxf(bx1, s_x1[j]);
                    float yy1 = fmaxf(by1, s_y1[j]);
                    float xx2 = fminf(bx2, s_x2[j]);
                    float yy2 = fminf(by2, s_y2[j]);
                    float inter = fmaxf(xx2 - xx1, 0.f) * fmaxf(yy2 - yy1, 0.f);
                    float denom = ai + s_area[j] - inter + 1e-9f;
                    if (inter > 0.5f * denom) m |= (1u << jr);
                }
            }
        }
        g_mask[((size_t)b * 1024 + i) * 32 + w] = m;  // always store (zeros too)
    }
}

// ---------------------------------------------------------------------------
// Kernel 4: chunked serial sweep (warp 0) + output. grid=BATCH, 256 threads.
// Per 32-row chunk: preload lane-column + decision-column into registers
// (64 independent LDGs), then the serial decision loop is register-local.
// ---------------------------------------------------------------------------
__global__ void __launch_bounds__(256) sweep_out_kernel(float* __restrict__ out) {
    __shared__ u32 s_remw[32];
    int tid  = threadIdx.x;
    int lane = tid & 31;
    int b    = blockIdx.x;

    if (tid < 32) {
        const u32* __restrict__ M = g_mask + (size_t)b * 1024 * 32;
        u32 rem = 0;
        for (int c = 0; c < 32; c++) {
            u32 mk[32], mc[32];
            #pragma unroll
            for (int k = 0; k < 32; k++) {
                int i = c * 32 + k;
                bool v = (i < KTOP);
                mk[k] = v ? M[i * 32 + lane] : 0u;   // my column
                mc[k] = v ? M[i * 32 + c]    : 0u;   // decision column
            }
            u32 cur = __shfl_sync(0xffffffffu, rem, c);
            u32 acc = 0;
            #pragma unroll
            for (int k = 0; k < 32; k++) {
                if (!((cur >> k) & 1u)) { acc |= mk[k]; cur |= mc[k]; }
            }
            rem |= acc;
        }
        s_remw[lane] = rem;
    }
    __syncthreads();

    for (int t = tid; t < KTOP; t += 256) {
        bool removed = (s_remw[t >> 5] >> (t & 31)) & 1u;
        int o = b * 1024 + t;
        float sc = g_top_score[o];
        float out_sc = (!removed && sc > 0.0f) ? sc : 0.0f;
        float4 bx = g_top_box[o];
        float* op = out + ((size_t)b * KTOP + t) * 6;
        op[0] = bx.x; op[1] = bx.y; op[2] = bx.z; op[3] = bx.w;
        op[4] = g_top_kind[o];
        op[5] = out_sc;
    }
}

// ---------------------------------------------------------------------------
extern "C" void kernel_launch(void* const* d_in, const int* in_sizes, int n_in,
                              void* d_out, int out_size) {
    bool dict_order = (in_sizes[1] != 2621440);
    Ptrs p;
    for (int i = 0; i < 5; i++) {
        if (dict_order) {
            p.cls[i] = (const float*)d_in[3 * i];
            p.reg[i] = (const float*)d_in[3 * i + 2];
        } else {
            p.cls[i] = (const float*)d_in[i];
            p.reg[i] = (const float*)d_in[10 + i];
        }
    }

    int total = BATCH * NPOS;
    decode_kernel<<<(total + 255) / 256, 256>>>(p);

    cudaFuncSetAttribute(select_kernel,
                         cudaFuncAttributeMaxDynamicSharedMemorySize, SEL_SMEM);
    select_kernel<<<BATCH, 1024, SEL_SMEM>>>();

    mask_kernel<<<dim3(16, BATCH), 256>>>();

    sweep_out_kernel<<<BATCH, 256>>>((float*)d_out);
}

// round 5
// speedup vs baseline: 4.2242x; 1.3095x over previous
#include <cuda_runtime.h>

typedef unsigned long long ull;
typedef unsigned int u32;

#define NPOS   21824
#define BATCH  8
#define KTOP   1000
#define NCLS   80
#define CAND_MAX 4096

// Scratch (no allocation allowed -> __device__ globals)
__device__ ull    g_keys[BATCH * NPOS];
__device__ float4 g_boxes[BATCH * NPOS];
__device__ float  g_kind[BATCH * NPOS];

// per-image selected top-1024 (SoA)
__device__ float4 g_top_box[BATCH * 1024];
__device__ float  g_top_kind[BATCH * 1024];
__device__ float  g_top_score[BATCH * 1024];
__device__ float  g_top_area[BATCH * 1024];
// suppression bit-matrix: [b][i][w], bit j-of-word => i suppresses j=w*32+bit
__device__ u32    g_mask[BATCH * 1024 * 32];

__constant__ int   c_off[5]    = {0, 16384, 20480, 21504, 21760};
__constant__ int   c_logw[5]   = {7, 6, 5, 4, 3};
__constant__ float c_stride[5] = {8.f, 16.f, 32.f, 64.f, 128.f};

struct Ptrs { const float* cls[5]; const float* reg[5]; };

// ---------------------------------------------------------------------------
// Kernel 1: decode all levels -> per-position (key, box, kind)
// key = (float_bits(score) << 32) | (0xFFFFFFFF - pos)
// ---------------------------------------------------------------------------
__global__ void decode_kernel(Ptrs p) {
    int gid = blockIdx.x * blockDim.x + threadIdx.x;
    if (gid >= BATCH * NPOS) return;
    int b   = gid / NPOS;
    int pos = gid - b * NPOS;

    int lev = 0;
    if      (pos >= c_off[4]) lev = 4;
    else if (pos >= c_off[3]) lev = 3;
    else if (pos >= c_off[2]) lev = 2;
    else if (pos >= c_off[1]) lev = 1;

    int local = pos - c_off[lev];
    int lw = c_logw[lev];
    int w  = 1 << lw;
    int hw = w * w;
    int y  = local >> lw;
    int x  = local & (w - 1);

    const float* __restrict__ cbase = p.cls[lev] + (size_t)b * NCLS * hw + local;
    float best = cbase[0];
    int   bi   = 0;
    #pragma unroll 8
    for (int c = 1; c < NCLS; c++) {
        float v = cbase[(size_t)c * hw];
        if (v > best) { best = v; bi = c; }
    }
    float score = (best > 0.05f) ? best : 0.0f;

    const float* __restrict__ rbase = p.reg[lev] + (size_t)b * 4 * hw + local;
    float s  = c_stride[lev];
    float r0 = rbase[0]      * s;
    float r1 = rbase[hw]     * s;
    float r2 = rbase[2 * hw] * s;
    float r3 = rbase[3 * hw] * s;
    float cx = ((float)x + 0.5f) * s;
    float cy = ((float)y + 0.5f) * s;

    g_boxes[gid] = make_float4(cx - r0, cy - r1, cx + r2, cy + r3);
    g_kind[gid]  = (float)bi;
    g_keys[gid]  = (((ull)__float_as_uint(score)) << 32) |
                   (ull)(0xFFFFFFFFu - (u32)pos);
}

// ---------------------------------------------------------------------------
// Kernel 2: per-image select top-1000 (exact radix select, parallel suffix
//           scan, candidate-list compaction), bitonic sort 1024, gather SoA.
// ---------------------------------------------------------------------------
#define SEL_SMEM ((NPOS + 1024 + CAND_MAX) * 8)   // 215552 bytes

__global__ void __launch_bounds__(1024, 1) select_kernel() {
    extern __shared__ ull sm[];
    ull* s_keys = sm;                    // NPOS
    ull* s_top  = sm + NPOS;             // 1024
    ull* s_cand = sm + NPOS + 1024;      // CAND_MAX

    __shared__ u32 s_hist[256];
    __shared__ int s_cnt, s_digit, s_rem, s_match;

    int tid  = threadIdx.x;
    int lane = tid & 31;
    int b    = blockIdx.x;
    const ull* __restrict__ gk = g_keys + (size_t)b * NPOS;

    for (int i = tid; i < NPOS; i += 1024) s_keys[i] = gk[i];

    ull prefix    = 0;
    int remaining = KTOP;
    bool list = false;
    int listn = 0;

    for (int shift = 56; shift >= 0; shift -= 8) {
        if (tid < 256) s_hist[tid] = 0;
        __syncthreads();

        ull himask = (shift == 56) ? 0ull : (~0ull << (shift + 8));
        const ull* src = list ? s_cand : s_keys;
        int n = list ? listn : NPOS;

        for (int i = tid; i < n; i += 1024) {
            ull k = src[i];
            if ((k & himask) == prefix) {
                u32 d      = (u32)(k >> shift) & 255u;
                u32 act    = __activemask();
                u32 peers  = __match_any_sync(act, d);
                int leader = __ffs(peers) - 1;
                if (lane == leader) atomicAdd(&s_hist[d], (u32)__popc(peers));
            }
        }
        __syncthreads();

        // ---- warp-0 parallel suffix scan of the 256-bin histogram ----
        if (tid < 32) {
            u32 h[8], suf[8];
            #pragma unroll
            for (int q = 0; q < 8; q++) h[q] = s_hist[tid * 8 + q];
            u32 run = 0;
            #pragma unroll
            for (int q = 7; q >= 0; q--) { run += h[q]; suf[q] = run; }
            u32 x = run;
            #pragma unroll
            for (int off = 1; off < 32; off <<= 1) {
                u32 y = __shfl_down_sync(0xffffffffu, x, off);
                if (lane + off < 32) x += y;
            }
            u32 excl = x - run;   // totals of lanes > me
            #pragma unroll
            for (int q = 0; q < 8; q++) s_hist[tid * 8 + q] = suf[q] + excl;
        }
        __syncthreads();
        if (tid < 256) {
            u32 suf  = s_hist[tid];
            u32 sufn = (tid == 255) ? 0u : s_hist[tid + 1];
            if (suf >= (u32)remaining && sufn < (u32)remaining) {
                s_digit = tid;
                s_rem   = remaining - (int)sufn;
                s_match = (int)(suf - sufn);
            }
        }
        __syncthreads();

        prefix |= ((ull)(u32)s_digit) << shift;
        remaining = s_rem;
        int matchcnt = s_match;

        // ---- one-time compaction full -> candidate list ----
        if (!list && matchcnt <= CAND_MAX && shift > 0) {
            ull pmask = ~0ull << shift;
            if (tid == 0) s_cnt = 0;
            __syncthreads();
            for (int i = tid; i < NPOS; i += 1024) {
                ull k = s_keys[i];
                if ((k & pmask) == prefix) {
                    u32 act    = __activemask();
                    u32 lt     = act & ((1u << lane) - 1u);
                    int rank   = __popc(lt);
                    int leader = __ffs(act) - 1;
                    int base   = 0;
                    if (lane == leader) base = atomicAdd(&s_cnt, __popc(act));
                    base = __shfl_sync(act, base, leader);
                    s_cand[base + rank] = k;
                }
            }
            __syncthreads();
            list  = true;
            listn = matchcnt;
        }
    }
    // prefix == exact KTOP-th largest key

    // ---- compact: all keys >= prefix (exactly KTOP) ----
    if (tid == 0) s_cnt = 0;
    s_top[tid] = 0;
    __syncthreads();
    for (int i = tid; i < NPOS; i += 1024) {
        ull k = s_keys[i];
        if (k >= prefix) {
            u32 act    = __activemask();
            u32 lt     = act & ((1u << lane) - 1u);
            int rank   = __popc(lt);
            int leader = __ffs(act) - 1;
            int base   = 0;
            if (lane == leader) base = atomicAdd(&s_cnt, __popc(act));
            base = __shfl_sync(act, base, leader);
            s_top[base + rank] = k;
        }
    }

    // ---- bitonic sort 1024, descending ----
    for (int k2 = 2; k2 <= 1024; k2 <<= 1) {
        for (int j = k2 >> 1; j > 0; j >>= 1) {
            __syncthreads();
            int ixj = tid ^ j;
            if (ixj > tid) {
                ull a = s_top[tid], c = s_top[ixj];
                bool desc = ((tid & k2) == 0);
                if (desc ? (a < c) : (a > c)) { s_top[tid] = c; s_top[ixj] = a; }
            }
        }
    }
    __syncthreads();

    // ---- gather into global SoA ----
    {
        ull k    = s_top[tid];
        float sc = __uint_as_float((u32)(k >> 32));
        u32 idx  = 0xFFFFFFFFu - (u32)(k & 0xFFFFFFFFull);
        float4 bx = make_float4(0.f, 0.f, 0.f, 0.f);
        float  kd = 0.f;
        if (tid < KTOP) {
            bx = g_boxes[(size_t)b * NPOS + idx];
            kd = g_kind[(size_t)b * NPOS + idx];
        }
        int o = b * 1024 + tid;
        g_top_box[o]   = bx;
        g_top_kind[o]  = kd;
        g_top_score[o] = sc;
        g_top_area[o]  = fmaxf(bx.z - bx.x, 0.f) * fmaxf(bx.w - bx.y, 0.f);
    }
}

// ---------------------------------------------------------------------------
// Kernel 3: suppression bit-matrix, spread across chip.
// Division-free IoU test: inter > 0.5*denom  <=>  iou > 0.5 (denom > 0).
// ---------------------------------------------------------------------------
__global__ void __launch_bounds__(256) mask_kernel() {
    __shared__ float s_x1[1024], s_y1[1024], s_x2[1024], s_y2[1024];
    __shared__ float s_area[1024], s_kind[1024];

    int tid = threadIdx.x;
    int b   = blockIdx.y;
    int r0  = blockIdx.x * 64;

    for (int t = tid; t < 1024; t += 256) {
        float4 bx = g_top_box[b * 1024 + t];
        s_x1[t] = bx.x; s_y1[t] = bx.y; s_x2[t] = bx.z; s_y2[t] = bx.w;
        s_area[t] = g_top_area[b * 1024 + t];
        s_kind[t] = g_top_kind[b * 1024 + t];
    }
    __syncthreads();

    int w  = tid & 31;
    int wi = tid >> 5;
    int jbase = w * 32;

    for (int k = 0; k < 8; k++) {
        int i = r0 + wi * 8 + k;
        u32 m = 0;
        if (i < KTOP && (jbase + 31) > i) {
            float bx1 = s_x1[i], by1 = s_y1[i], bx2 = s_x2[i], by2 = s_y2[i];
            float ai = s_area[i], ki = s_kind[i];
            #pragma unroll
            for (int it = 0; it < 32; it++) {
                int jr = (it + w) & 31;       // rotate -> conflict-free banks
                int j  = jbase + jr;
                if (j > i && j < KTOP && s_kind[j] == ki) {
                    float xx1 = fmaxf(bx1, s_x1[j]);
                    float yy1 = fmaxf(by1, s_y1[j]);
                    float xx2 = fminf(bx2, s_x2[j]);
                    float yy2 = fminf(by2, s_y2[j]);
                    float inter = fmaxf(xx2 - xx1, 0.f) * fmaxf(yy2 - yy1, 0.f);
                    float denom = ai + s_area[j] - inter + 1e-9f;
                    if (inter > 0.5f * denom) m |= (1u << jr);
                }
            }
        }
        g_mask[((size_t)b * 1024 + i) * 32 + w] = m;
    }
}

// ---------------------------------------------------------------------------
// Kernel 4: sweep from SHARED mask + output. grid=BATCH, 1024 threads.
// Mask staged to smem coalesced; serial sweep reads conflict-free LDS.
// ---------------------------------------------------------------------------
#define SWEEP_SMEM (1024 * 32 * 4)   // 131072 bytes

__global__ void __launch_bounds__(1024, 1) sweep_out_kernel(float* __restrict__ out) {
    extern __shared__ u32 s_mask[];
    __shared__ u32 s_remw[32];
    int tid  = threadIdx.x;
    int lane = tid & 31;
    int b    = blockIdx.x;

    // stage 128KB mask into shared (coalesced uint4)
    const uint4* __restrict__ M4 = (const uint4*)(g_mask + (size_t)b * 1024 * 32);
    uint4* S4 = (uint4*)s_mask;
    for (int i = tid; i < 1024 * 32 / 4; i += 1024) S4[i] = M4[i];
    __syncthreads();

    if (tid < 32) {
        u32 rem = 0;
        for (int c = 0; c < 32; c++) {
            u32 mk[32], mc[32];
            #pragma unroll
            for (int k = 0; k < 32; k++) {
                int i = c * 32 + k;
                mk[k] = s_mask[i * 32 + lane];   // bank = lane (conflict-free)
                mc[k] = s_mask[i * 32 + c];      // broadcast
            }
            u32 cur = __shfl_sync(0xffffffffu, rem, c);
            u32 acc = 0;
            #pragma unroll
            for (int k = 0; k < 32; k++) {
                if (!((cur >> k) & 1u)) { acc |= mk[k]; cur |= mc[k]; }
            }
            rem |= acc;
        }
        s_remw[lane] = rem;
    }
    __syncthreads();

    for (int t = tid; t < KTOP; t += 1024) {
        bool removed = (s_remw[t >> 5] >> (t & 31)) & 1u;
        int o = b * 1024 + t;
        float sc = g_top_score[o];
        float out_sc = (!removed && sc > 0.0f) ? sc : 0.0f;
        float4 bx = g_top_box[o];
        float* op = out + ((size_t)b * KTOP + t) * 6;
        op[0] = bx.x; op[1] = bx.y; op[2] = bx.z; op[3] = bx.w;
        op[4] = g_top_kind[o];
        op[5] = out_sc;
    }
}

// ---------------------------------------------------------------------------
extern "C" void kernel_launch(void* const* d_in, const int* in_sizes, int n_in,
                              void* d_out, int out_size) {
    bool dict_order = (in_sizes[1] != 2621440);
    Ptrs p;
    for (int i = 0; i < 5; i++) {
        if (dict_order) {
            p.cls[i] = (const float*)d_in[3 * i];
            p.reg[i] = (const float*)d_in[3 * i + 2];
        } else {
            p.cls[i] = (const float*)d_in[i];
            p.reg[i] = (const float*)d_in[10 + i];
        }
    }

    int total = BATCH * NPOS;
    decode_kernel<<<(total + 255) / 256, 256>>>(p);

    cudaFuncSetAttribute(select_kernel,
                         cudaFuncAttributeMaxDynamicSharedMemorySize, SEL_SMEM);
    select_kernel<<<BATCH, 1024, SEL_SMEM>>>();

    mask_kernel<<<dim3(16, BATCH), 256>>>();

    cudaFuncSetAttribute(sweep_out_kernel,
                         cudaFuncAttributeMaxDynamicSharedMemorySize, SWEEP_SMEM);
    sweep_out_kernel<<<BATCH, 1024, SWEEP_SMEM>>>((float*)d_out);
}